// round 10
// baseline (speedup 1.0000x reference)
#include <cuda_runtime.h>

#define BATCH 16
#define CHN   8
#define HH    512
#define WW    512
#define TW    128
#define TH    8
#define TILES_X (WW / TW)   // 4
#define TILES_Y (HH / TH)   // 64
#define NBLK (TILES_X * TILES_Y * BATCH)  // 4096

#define EPR    136                  // pair entries per row (8B each) -> 1088B pitch
#define ROWB   (EPR * 8)            // 1088
#define NROWS  (TH + 2)             // 10
#define CSTRIDE (NROWS * ROWB)      // 10880 (one channel slot)

// Scratch (device globals: allocation-free rule)
__device__ float g_y[BATCH * CHN * HH * WW];
__device__ float g_part[NBLK * 16];
__device__ float g_scale[CHN];
__device__ float g_shift[CHN];

// ---------- helpers ----------
__device__ __forceinline__ void fma2(unsigned long long& d, unsigned long long a,
                                     unsigned long long b) {
    asm("fma.rn.f32x2 %0, %1, %2, %0;" : "+l"(d) : "l"(a), "l"(b));
}
__device__ __forceinline__ void add2(unsigned long long& d, unsigned long long a) {
    asm("add.rn.f32x2 %0, %0, %1;" : "+l"(d) : "l"(a));
}
__device__ __forceinline__ float2 up2(unsigned long long v) {
    float2 f;
    asm("mov.b64 {%0, %1}, %2;" : "=f"(f.x), "=f"(f.y) : "l"(v));
    return f;
}
__device__ __forceinline__ int swz(int e) {           // XOR swizzle on pair-entry index
    return e ^ (((e >> 4) & 7) << 1);
}
__device__ __forceinline__ void stpair(unsigned addr, float a, float b) {
    asm volatile("st.shared.v2.f32 [%0], {%1, %2};" :: "r"(addr), "f"(a), "f"(b));
}
#define LDS128I(lo, hi, addr, IMM) \
    asm("ld.shared.v2.u64 {%0, %1}, [%2+" IMM "];" : "=l"(lo), "=l"(hi) : "r"(addr))

// taps: 8 couts x (3 taps x 4 pairs) per (cin,kh); adjacent-cout weight pairs
// fetched with one broadcast LDS.128.
__device__ __forceinline__ void taps(unsigned long long acc[8][4],
                                     const ulonglong2 L[5],
                                     const unsigned long long* __restrict__ wrow) {
    #pragma unroll
    for (int cp = 0; cp < 4; cp++) {
        ulonglong2 WA = *(const ulonglong2*)(wrow + 2 * cp);
        ulonglong2 WB = *(const ulonglong2*)(wrow + 8 + 2 * cp);
        ulonglong2 WC = *(const ulonglong2*)(wrow + 16 + 2 * cp);
        const int c0 = 2 * cp, c1 = 2 * cp + 1;
        #pragma unroll
        for (int m = 0; m < 4; m++) {
            fma2(acc[c0][m], L[m].x, WA.x);
            fma2(acc[c1][m], L[m].x, WA.y);
            fma2(acc[c0][m], L[m].y, WB.x);
            fma2(acc[c1][m], L[m].y, WB.y);
            fma2(acc[c0][m], L[m + 1].x, WC.x);
            fma2(acc[c1][m], L[m + 1].x, WC.y);
        }
    }
}

// ---------- Kernel 1: conv3x3 + bias -> g_y, per-block channel sum/sumsq ----------
// 128 threads: tx = tid&15 (8-px group), ty = tid>>4 (row). 8 couts per thread.
// Software-pipelined: 2-slot smem ring over input channels; LDG prefetch of
// channel c+1 held in registers during compute of channel c.
__global__ __launch_bounds__(128, 4) void conv_kernel(
    const float* __restrict__ x, const float* __restrict__ lin_w,
    const float* __restrict__ lin_b) {
    __shared__ char s_tile[2 * CSTRIDE];              // 21760 B (2 channel slots)
    __shared__ float2 s_w[CHN * 9 * 8];               // (w,w) pairs: 4608 B
    __shared__ float2 s_bias[8];

    const int tid = threadIdx.x;
    const int tx = tid & 15;          // 8-px group
    const int ty = tid >> 4;          // row 0..7
    const int bw = blockIdx.x, bh = blockIdx.y, b = blockIdx.z;
    const int col0 = bw * TW, row0 = bh * TH;
    const unsigned sbase = (unsigned)__cvta_generic_to_shared(s_tile);

    // Weights: s_w[(cin*9 + tap)*8 + cout] = (w, w)
    for (int i = tid; i < CHN * 9 * 8; i += 128) {
        int cout = i & 7;
        int t = (i >> 3) % 9;
        int cin = i / 72;
        float w = lin_w[(cin * 8 + cout) * 9 + t];
        s_w[i] = make_float2(w, w);
    }
    if (tid < 8) {
        float bs = 0.f;
        #pragma unroll
        for (int cin = 0; cin < 8; cin++) bs += lin_b[cin * 8 + tid];
        s_bias[tid] = make_float2(bs, bs);
    }

    // Accumulators: 8 couts x 4 pixel-pairs; bias added at epilogue.
    unsigned long long acc[8][4];
    #pragma unroll
    for (int co = 0; co < 8; co++)
        #pragma unroll
        for (int m = 0; m < 4; m++) acc[co][m] = 0ull;

    // Thread's 5 LDS.128 base offsets (row ty, slot 0)
    unsigned off0, off1, off2, off3, off4;
    {
        int e0 = 8 * tx;
        off0 = sbase + ty * ROWB + swz(e0 + 0) * 8;
        off1 = sbase + ty * ROWB + swz(e0 + 2) * 8;
        off2 = sbase + ty * ROWB + swz(e0 + 4) * 8;
        off3 = sbase + ty * ROWB + swz(e0 + 6) * 8;
        off4 = sbase + ty * ROWB + swz(e0 + 8) * 8;
    }
    const unsigned long long* __restrict__ swp = (const unsigned long long*)s_w;

    // Per-channel staging decomposition (per thread):
    //   items j=0,1,2: linear idx = tid + 128*j over 320 = 10 rows x 32 chunks
    //   edge: tid<20 -> (row tid>>1, side tid&1)
    const int r0i = tid >> 5, chk = tid & 31;
    const int gcc = col0 + chk * 4;
    const bool rowok2 = (tid < 64);
    const int er = tid >> 1, eside = tid & 1;

    // prefetch registers
    float4 pA0, pA1, pA2;
    float pb0, pb1, pb2, pe0, pe1;

    // ---- LDG prefetch macro (channel cc -> regs) ----
#define LDGCH(cc)                                                              \
    {                                                                          \
        const float* xc = x + ((size_t)(b * CHN + (cc))) * (HH * WW);          \
        {   int gr = row0 + r0i - 1;                                           \
            bool rok = (unsigned)gr < HH;                                      \
            const float* rp = xc + (size_t)gr * WW;                            \
            pA0 = rok ? *(const float4*)(rp + gcc)                             \
                      : make_float4(0.f, 0.f, 0.f, 0.f);                       \
            pb0 = (rok && gcc + 4 < WW) ? rp[gcc + 4] : 0.f; }                 \
        {   int gr = row0 + r0i + 3;                                           \
            bool rok = (unsigned)gr < HH;                                      \
            const float* rp = xc + (size_t)gr * WW;                            \
            pA1 = rok ? *(const float4*)(rp + gcc)                             \
                      : make_float4(0.f, 0.f, 0.f, 0.f);                       \
            pb1 = (rok && gcc + 4 < WW) ? rp[gcc + 4] : 0.f; }                 \
        pA2 = make_float4(0.f, 0.f, 0.f, 0.f); pb2 = 0.f;                      \
        if (rowok2) {                                                          \
            int gr = row0 + r0i + 7;                                           \
            bool rok = (unsigned)gr < HH;                                      \
            const float* rp = xc + (size_t)gr * WW;                            \
            if (rok) { pA2 = *(const float4*)(rp + gcc);                       \
                       if (gcc + 4 < WW) pb2 = rp[gcc + 4]; } }                \
        pe0 = 0.f; pe1 = 0.f;                                                  \
        if (tid < 20) {                                                        \
            int gr = row0 + er - 1;                                            \
            bool rok = (unsigned)gr < HH;                                      \
            const float* rp = xc + (size_t)gr * WW;                            \
            if (!eside) {                                                      \
                if (rok && col0 >= 1) pe0 = rp[col0 - 1];                      \
                if (rok) pe1 = rp[col0];                                       \
            } else {                                                           \
                if (rok && col0 + 128 < WW) pe0 = rp[col0 + 128];              \
            }                                                                  \
        }                                                                      \
    }

    // ---- STS macro (regs -> slot) ----
#define STSCH(slotoff)                                                         \
    {                                                                          \
        const unsigned rb = sbase + (slotoff);                                 \
        const int e = chk * 4 + 1;                                             \
        {   unsigned ra = rb + r0i * ROWB;                                     \
            stpair(ra + swz(e) * 8,     pA0.x, pA0.y);                         \
            stpair(ra + swz(e + 1) * 8, pA0.y, pA0.z);                         \
            stpair(ra + swz(e + 2) * 8, pA0.z, pA0.w);                         \
            stpair(ra + swz(e + 3) * 8, pA0.w, pb0); }                         \
        {   unsigned ra = rb + (r0i + 4) * ROWB;                               \
            stpair(ra + swz(e) * 8,     pA1.x, pA1.y);                         \
            stpair(ra + swz(e + 1) * 8, pA1.y, pA1.z);                         \
            stpair(ra + swz(e + 2) * 8, pA1.z, pA1.w);                         \
            stpair(ra + swz(e + 3) * 8, pA1.w, pb1); }                         \
        if (rowok2) {                                                          \
            unsigned ra = rb + (r0i + 8) * ROWB;                               \
            stpair(ra + swz(e) * 8,     pA2.x, pA2.y);                         \
            stpair(ra + swz(e + 1) * 8, pA2.y, pA2.z);                         \
            stpair(ra + swz(e + 2) * 8, pA2.z, pA2.w);                         \
            stpair(ra + swz(e + 3) * 8, pA2.w, pb2); }                         \
        if (tid < 20) {                                                        \
            unsigned ra = rb + er * ROWB;                                      \
            int ee = eside ? 129 : 0;                                          \
            stpair(ra + swz(ee) * 8, pe0, pe1);                                \
        }                                                                      \
    }

    LDGCH(0);                      // prologue prefetch

    #pragma unroll 1
    for (int c = 0; c < 8; c++) {
        const unsigned slotoff = (unsigned)(c & 1) * CSTRIDE;
        STSCH(slotoff);            // store channel c (prefetched last iter)
        if (c < 7) LDGCH(c + 1);   // prefetch next channel (in flight during compute)
        __syncthreads();           // channel c visible; slot safety via prior sync

        unsigned o0 = off0 + slotoff, o1 = off1 + slotoff, o2 = off2 + slotoff,
                 o3 = off3 + slotoff, o4 = off4 + slotoff;
        {   // kh = 0
            ulonglong2 L[5];
            LDS128I(L[0].x, L[0].y, o0, "0");
            LDS128I(L[1].x, L[1].y, o1, "0");
            LDS128I(L[2].x, L[2].y, o2, "0");
            LDS128I(L[3].x, L[3].y, o3, "0");
            LDS128I(L[4].x, L[4].y, o4, "0");
            taps(acc, L, swp + (c * 9 + 0) * 8);
        }
        {   // kh = 1
            ulonglong2 L[5];
            LDS128I(L[0].x, L[0].y, o0, "1088");
            LDS128I(L[1].x, L[1].y, o1, "1088");
            LDS128I(L[2].x, L[2].y, o2, "1088");
            LDS128I(L[3].x, L[3].y, o3, "1088");
            LDS128I(L[4].x, L[4].y, o4, "1088");
            taps(acc, L, swp + (c * 9 + 3) * 8);
        }
        {   // kh = 2
            ulonglong2 L[5];
            LDS128I(L[0].x, L[0].y, o0, "2176");
            LDS128I(L[1].x, L[1].y, o1, "2176");
            LDS128I(L[2].x, L[2].y, o2, "2176");
            LDS128I(L[3].x, L[3].y, o3, "2176");
            LDS128I(L[4].x, L[4].y, o4, "2176");
            taps(acc, L, swp + (c * 9 + 6) * 8);
        }
    }

    // ---- epilogue: add bias, store y, channel sums ----
    const int orow = row0 + ty;
    float vals[16];
    #pragma unroll
    for (int co = 0; co < 8; co++) {
        unsigned long long bz = ((const unsigned long long*)s_bias)[co];
        #pragma unroll
        for (int m = 0; m < 4; m++) add2(acc[co][m], bz);
        size_t off = ((size_t)(b * 8 + co) * HH + orow) * WW + col0 + 8 * tx;
        *(ulonglong2*)(g_y + off)     = make_ulonglong2(acc[co][0], acc[co][1]);
        *(ulonglong2*)(g_y + off + 4) = make_ulonglong2(acc[co][2], acc[co][3]);
        unsigned long long ss = 0ull, sq = 0ull;
        #pragma unroll
        for (int m = 0; m < 4; m++) {
            add2(ss, acc[co][m]);
            fma2(sq, acc[co][m], acc[co][m]);
        }
        float2 fs = up2(ss), fq = up2(sq);
        vals[co] = fs.x + fs.y;
        vals[8 + co] = fq.x + fq.y;
    }
    #pragma unroll
    for (int v = 0; v < 16; v++) {
        float t = vals[v];
        #pragma unroll
        for (int o = 16; o > 0; o >>= 1) t += __shfl_xor_sync(0xFFFFFFFFu, t, o);
        vals[v] = t;
    }
    float* sred = (float*)s_tile;   // slot 0 start; c=7 readers used slot 1
    int wid = tid >> 5, lane = tid & 31;
    if (lane == 0) {
        #pragma unroll
        for (int v = 0; v < 16; v++) sred[wid * 16 + v] = vals[v];
    }
    __syncthreads();
    if (tid < 16) {
        float t = sred[tid] + sred[16 + tid] + sred[32 + tid] + sred[48 + tid];
        int blin = (b * gridDim.y + bh) * gridDim.x + bw;
        g_part[blin * 16 + tid] = t;
    }
#undef LDGCH
#undef STSCH
}

// ---------- Kernel 2: finalize statistics ----------
__global__ __launch_bounds__(1024) void stats_kernel(const float* __restrict__ gamma,
                                                     const float* __restrict__ beta) {
    __shared__ float red[1024];
    int tid = threadIdx.x;
    int v = tid & 15, g = tid >> 4;   // 64 groups
    float s = 0.f;
    for (int i = g; i < NBLK; i += 64) s += g_part[i * 16 + v];
    red[tid] = s;
    __syncthreads();
    float tot = 0.f;
    if (tid < 16) {
        #pragma unroll
        for (int gg = 0; gg < 64; gg++) tot += red[gg * 16 + tid];
    }
    __syncthreads();
    if (tid < 16) red[tid] = tot;
    __syncthreads();
    if (tid < 8) {
        const float n = (float)(BATCH * HH * WW);
        float mean = red[tid] / n;
        float var = red[tid + 8] / n - mean * mean;
        float sc = gamma[tid] * rsqrtf(var + 1e-5f);
        g_scale[tid] = sc;
        g_shift[tid] = beta[tid] - mean * sc;
    }
}

// ---------- Kernel 3: normalize + ReLU ----------
__global__ __launch_bounds__(256) void norm_kernel(float* __restrict__ out) {
    __shared__ float ssc[8], ssh[8];
    if (threadIdx.x < 8) {
        ssc[threadIdx.x] = g_scale[threadIdx.x];
        ssh[threadIdx.x] = g_shift[threadIdx.x];
    }
    __syncthreads();
    int i = blockIdx.x * 256 + threadIdx.x;
    int c = (i >> 16) & 7;
    float4 v = ((const float4*)g_y)[i];
    float s = ssc[c], h = ssh[c];
    v.x = fmaxf(fmaf(v.x, s, h), 0.f);
    v.y = fmaxf(fmaf(v.y, s, h), 0.f);
    v.z = fmaxf(fmaf(v.z, s, h), 0.f);
    v.w = fmaxf(fmaf(v.w, s, h), 0.f);
    ((float4*)out)[i] = v;
}

extern "C" void kernel_launch(void* const* d_in, const int* in_sizes, int n_in,
                              void* d_out, int out_size) {
    const float* x     = (const float*)d_in[0];
    const float* lin_w = (const float*)d_in[1];
    const float* lin_b = (const float*)d_in[2];
    const float* gamma = (const float*)d_in[3];
    const float* beta  = (const float*)d_in[4];
    float* out = (float*)d_out;

    dim3 grid(TILES_X, TILES_Y, BATCH);
    conv_kernel<<<grid, 128>>>(x, lin_w, lin_b);
    stats_kernel<<<1, 1024>>>(gamma, beta);
    int n4 = BATCH * CHN * HH * WW / 4;
    norm_kernel<<<n4 / 256, 256>>>(out);
}

// round 12
// speedup vs baseline: 1.3724x; 1.3724x over previous
#include <cuda_runtime.h>

#define BATCH 16
#define CHN   8
#define HH    512
#define WW    512
#define HW    (HH * WW)
#define TW    128
#define TH    8
#define TILES_X (WW / TW)   // 4
#define TILES_Y (HH / TH)   // 64
#define NBLK (TILES_X * TILES_Y * BATCH)  // 4096

#define EPR    136                  // pair entries per row (8B each) -> 1088B pitch
#define ROWB   (EPR * 8)            // 1088
#define NROWS  (TH + 2)             // 10
#define CSTRIDE (NROWS * ROWB)      // 10880 (one channel slot)

// Scratch (device globals: allocation-free rule)
__device__ float g_y[BATCH * CHN * HH * WW];
__device__ float g_part[NBLK * 16];
__device__ float g_scale[CHN];
__device__ float g_shift[CHN];
__device__ float g_zero[8];          // zero-initialized, never written: OOB redirect

// ---------- helpers ----------
__device__ __forceinline__ void fma2(unsigned long long& d, unsigned long long a,
                                     unsigned long long b) {
    asm("fma.rn.f32x2 %0, %1, %2, %0;" : "+l"(d) : "l"(a), "l"(b));
}
__device__ __forceinline__ void add2(unsigned long long& d, unsigned long long a) {
    asm("add.rn.f32x2 %0, %0, %1;" : "+l"(d) : "l"(a));
}
__device__ __forceinline__ float2 up2(unsigned long long v) {
    float2 f;
    asm("mov.b64 {%0, %1}, %2;" : "=f"(f.x), "=f"(f.y) : "l"(v));
    return f;
}
__device__ __forceinline__ int swz(int e) {           // XOR swizzle on pair-entry index
    return e ^ (((e >> 4) & 7) << 1);
}
__device__ __forceinline__ void stpair(unsigned addr, float a, float b) {
    asm volatile("st.shared.v2.f32 [%0], {%1, %2};" :: "r"(addr), "f"(a), "f"(b));
}
#define LDS128I(lo, hi, addr, IMM) \
    asm("ld.shared.v2.u64 {%0, %1}, [%2+" IMM "];" : "=l"(lo), "=l"(hi) : "r"(addr))

// taps: 8 couts x (3 taps x 4 pairs) per (cin,kh); adjacent-cout weight pairs
// fetched with one broadcast LDS.128.
__device__ __forceinline__ void taps(unsigned long long acc[8][4],
                                     const ulonglong2 L[5],
                                     const unsigned long long* __restrict__ wrow) {
    #pragma unroll
    for (int cp = 0; cp < 4; cp++) {
        ulonglong2 WA = *(const ulonglong2*)(wrow + 2 * cp);
        ulonglong2 WB = *(const ulonglong2*)(wrow + 8 + 2 * cp);
        ulonglong2 WC = *(const ulonglong2*)(wrow + 16 + 2 * cp);
        const int c0 = 2 * cp, c1 = 2 * cp + 1;
        #pragma unroll
        for (int m = 0; m < 4; m++) {
            fma2(acc[c0][m], L[m].x, WA.x);
            fma2(acc[c1][m], L[m].x, WA.y);
            fma2(acc[c0][m], L[m].y, WB.x);
            fma2(acc[c1][m], L[m].y, WB.y);
            fma2(acc[c0][m], L[m + 1].x, WC.x);
            fma2(acc[c1][m], L[m + 1].x, WC.y);
        }
    }
}

// ---------- Kernel 1: conv3x3 + bias -> g_y, per-block channel sum/sumsq ----------
// 128 threads: tx = tid&15 (8-px group), ty = tid>>4 (row). 8 couts per thread.
// 2-slot smem ring over input channels; LDG prefetch of channel c+1 in flight
// during compute of channel c. All bounds logic hoisted into one-time
// zero-row-redirected pointers (+per-pointer stride HW or 0).
__global__ __launch_bounds__(128, 4) void conv_kernel(
    const float* __restrict__ x, const float* __restrict__ lin_w,
    const float* __restrict__ lin_b) {
    __shared__ char s_tile[2 * CSTRIDE];              // 21760 B (2 channel slots)
    __shared__ float2 s_w[CHN * 9 * 8];               // (w,w) pairs: 4608 B
    __shared__ float2 s_bias[8];

    const int tid = threadIdx.x;
    const int tx = tid & 15;          // 8-px group
    const int ty = tid >> 4;          // row 0..7
    const int bw = blockIdx.x, bh = blockIdx.y, b = blockIdx.z;
    const int col0 = bw * TW, row0 = bh * TH;
    const unsigned sbase = (unsigned)__cvta_generic_to_shared(s_tile);

    // Weights: s_w[(cin*9 + tap)*8 + cout] = (w, w)
    for (int i = tid; i < CHN * 9 * 8; i += 128) {
        int cout = i & 7;
        int t = (i >> 3) % 9;
        int cin = i / 72;
        float w = lin_w[(cin * 8 + cout) * 9 + t];
        s_w[i] = make_float2(w, w);
    }
    if (tid < 8) {
        float bs = 0.f;
        #pragma unroll
        for (int cin = 0; cin < 8; cin++) bs += lin_b[cin * 8 + tid];
        s_bias[tid] = make_float2(bs, bs);
    }

    // Accumulators (bias added in epilogue)
    unsigned long long acc[8][4];
    #pragma unroll
    for (int co = 0; co < 8; co++)
        #pragma unroll
        for (int m = 0; m < 4; m++) acc[co][m] = 0ull;

    // Thread's 5 LDS.128 base offsets (row ty, slot 0)
    unsigned off0, off1, off2, off3, off4;
    {
        int e0 = 8 * tx;
        off0 = sbase + ty * ROWB + swz(e0 + 0) * 8;
        off1 = sbase + ty * ROWB + swz(e0 + 2) * 8;
        off2 = sbase + ty * ROWB + swz(e0 + 4) * 8;
        off3 = sbase + ty * ROWB + swz(e0 + 6) * 8;
        off4 = sbase + ty * ROWB + swz(e0 + 8) * 8;
    }

    // ---- one-time staging pointer setup (channel 0; advance by stride) ----
    const int r0i = tid >> 5, chk = tid & 31;   // staging row group / 4-col chunk
    const int gcc = col0 + chk * 4;
    const bool rowok2 = (tid < 64);
    const int er = tid >> 1, eside = tid & 1;

    const float* xb = x + (size_t)b * CHN * HW;   // channel 0 base

    const float *pr0, *pr1, *pr2, *ph0, *ph1, *ph2, *pea, *peb;
    int st0, st1, st2, sh0, sh1, sh2, sea, seb;
    {
        int gr0 = row0 + r0i - 1, gr1 = row0 + r0i + 3, gr2 = row0 + r0i + 7;
        bool k0 = (unsigned)gr0 < HH, k1 = (unsigned)gr1 < HH,
             k2 = rowok2 && (unsigned)gr2 < HH;
        bool hc = (gcc + 4 < WW);
        pr0 = k0 ? xb + (size_t)gr0 * WW + gcc : g_zero;  st0 = k0 ? HW : 0;
        pr1 = k1 ? xb + (size_t)gr1 * WW + gcc : g_zero;  st1 = k1 ? HW : 0;
        pr2 = k2 ? xb + (size_t)gr2 * WW + gcc : g_zero;  st2 = k2 ? HW : 0;
        ph0 = (k0 && hc) ? xb + (size_t)gr0 * WW + gcc + 4 : g_zero;  sh0 = (k0 && hc) ? HW : 0;
        ph1 = (k1 && hc) ? xb + (size_t)gr1 * WW + gcc + 4 : g_zero;  sh1 = (k1 && hc) ? HW : 0;
        ph2 = (k2 && hc) ? xb + (size_t)gr2 * WW + gcc + 4 : g_zero;  sh2 = (k2 && hc) ? HW : 0;
        // edge (tid<20): row row0+er-1; eside 0 -> entries (x[col0-1], x[col0]),
        // eside 1 -> (x[col0+128], 0)
        int gre = row0 + er - 1;
        bool ke = (tid < 20) && ((unsigned)gre < HH);
        bool a_ok = ke && (eside ? (col0 + 128 < WW) : (col0 >= 1));
        bool b_ok = ke && !eside;
        const float* rpe = xb + (size_t)gre * WW;
        pea = a_ok ? (eside ? rpe + col0 + 128 : rpe + col0 - 1) : g_zero;
        sea = a_ok ? HW : 0;
        peb = b_ok ? rpe + col0 : g_zero;
        seb = b_ok ? HW : 0;
    }

    // prefetch registers
    float4 pA0, pA1, pA2;
    float pb0, pb1, pb2, pe0, pe1;

#define LDGCH()                                                                \
    {                                                                          \
        pA0 = *(const float4*)pr0;  pb0 = ph0[0];                              \
        pA1 = *(const float4*)pr1;  pb1 = ph1[0];                              \
        pA2 = *(const float4*)pr2;  pb2 = ph2[0];                              \
        pe0 = pea[0];  pe1 = peb[0];                                           \
        pr0 += st0; pr1 += st1; pr2 += st2;                                    \
        ph0 += sh0; ph1 += sh1; ph2 += sh2;                                    \
        pea += sea; peb += seb;                                                \
    }

#define STSCH(slotoff)                                                         \
    {                                                                          \
        const unsigned rb = sbase + (slotoff);                                 \
        const int e = chk * 4 + 1;                                             \
        {   unsigned ra = rb + r0i * ROWB;                                     \
            stpair(ra + swz(e) * 8,     pA0.x, pA0.y);                         \
            stpair(ra + swz(e + 1) * 8, pA0.y, pA0.z);                         \
            stpair(ra + swz(e + 2) * 8, pA0.z, pA0.w);                         \
            stpair(ra + swz(e + 3) * 8, pA0.w, pb0); }                         \
        {   unsigned ra = rb + (r0i + 4) * ROWB;                               \
            stpair(ra + swz(e) * 8,     pA1.x, pA1.y);                         \
            stpair(ra + swz(e + 1) * 8, pA1.y, pA1.z);                         \
            stpair(ra + swz(e + 2) * 8, pA1.z, pA1.w);                         \
            stpair(ra + swz(e + 3) * 8, pA1.w, pb1); }                         \
        if (rowok2) {                                                          \
            unsigned ra = rb + (r0i + 8) * ROWB;                               \
            stpair(ra + swz(e) * 8,     pA2.x, pA2.y);                         \
            stpair(ra + swz(e + 1) * 8, pA2.y, pA2.z);                         \
            stpair(ra + swz(e + 2) * 8, pA2.z, pA2.w);                         \
            stpair(ra + swz(e + 3) * 8, pA2.w, pb2); }                         \
        if (tid < 20) {                                                        \
            unsigned ra = rb + er * ROWB;                                      \
            int ee = eside ? 129 : 0;                                          \
            stpair(ra + swz(ee) * 8, pe0, pe1);                                \
        }                                                                      \
    }

    const unsigned long long* __restrict__ wp = (const unsigned long long*)s_w;

    LDGCH();                       // prologue prefetch (channel 0)

    #pragma unroll 1
    for (int c = 0; c < 8; c++) {
        const unsigned slotoff = (unsigned)(c & 1) * CSTRIDE;
        STSCH(slotoff);            // store channel c (prefetched last iter)
        if (c < 7) LDGCH();        // prefetch next channel (in flight during compute)
        __syncthreads();

        unsigned o0 = off0 + slotoff, o1 = off1 + slotoff, o2 = off2 + slotoff,
                 o3 = off3 + slotoff, o4 = off4 + slotoff;
        {   // kh = 0
            ulonglong2 L[5];
            LDS128I(L[0].x, L[0].y, o0, "0");
            LDS128I(L[1].x, L[1].y, o1, "0");
            LDS128I(L[2].x, L[2].y, o2, "0");
            LDS128I(L[3].x, L[3].y, o3, "0");
            LDS128I(L[4].x, L[4].y, o4, "0");
            taps(acc, L, wp);
        }
        {   // kh = 1
            ulonglong2 L[5];
            LDS128I(L[0].x, L[0].y, o0, "1088");
            LDS128I(L[1].x, L[1].y, o1, "1088");
            LDS128I(L[2].x, L[2].y, o2, "1088");
            LDS128I(L[3].x, L[3].y, o3, "1088");
            LDS128I(L[4].x, L[4].y, o4, "1088");
            taps(acc, L, wp + 24);
        }
        {   // kh = 2
            ulonglong2 L[5];
            LDS128I(L[0].x, L[0].y, o0, "2176");
            LDS128I(L[1].x, L[1].y, o1, "2176");
            LDS128I(L[2].x, L[2].y, o2, "2176");
            LDS128I(L[3].x, L[3].y, o3, "2176");
            LDS128I(L[4].x, L[4].y, o4, "2176");
            taps(acc, L, wp + 48);
        }
        wp += 72;
    }

    // ---- epilogue: add bias, store y, channel sums ----
    const int orow = row0 + ty;
    float vals[16];
    #pragma unroll
    for (int co = 0; co < 8; co++) {
        unsigned long long bz = ((const unsigned long long*)s_bias)[co];
        #pragma unroll
        for (int m = 0; m < 4; m++) add2(acc[co][m], bz);
        size_t off = ((size_t)(b * 8 + co) * HH + orow) * WW + col0 + 8 * tx;
        *(ulonglong2*)(g_y + off)     = make_ulonglong2(acc[co][0], acc[co][1]);
        *(ulonglong2*)(g_y + off + 4) = make_ulonglong2(acc[co][2], acc[co][3]);
        unsigned long long ss = 0ull, sq = 0ull;
        #pragma unroll
        for (int m = 0; m < 4; m++) {
            add2(ss, acc[co][m]);
            fma2(sq, acc[co][m], acc[co][m]);
        }
        float2 fs = up2(ss), fq = up2(sq);
        vals[co] = fs.x + fs.y;
        vals[8 + co] = fq.x + fq.y;
    }
    #pragma unroll
    for (int v = 0; v < 16; v++) {
        float t = vals[v];
        #pragma unroll
        for (int o = 16; o > 0; o >>= 1) t += __shfl_xor_sync(0xFFFFFFFFu, t, o);
        vals[v] = t;
    }
    float* sred = (float*)s_tile;   // slot 0 start; final compute read slot 1
    int wid = tid >> 5, lane = tid & 31;
    if (lane == 0) {
        #pragma unroll
        for (int v = 0; v < 16; v++) sred[wid * 16 + v] = vals[v];
    }
    __syncthreads();
    if (tid < 16) {
        float t = sred[tid] + sred[16 + tid] + sred[32 + tid] + sred[48 + tid];
        int blin = (b * gridDim.y + bh) * gridDim.x + bw;
        g_part[blin * 16 + tid] = t;
    }
#undef LDGCH
#undef STSCH
}

// ---------- Kernel 2: finalize statistics ----------
__global__ __launch_bounds__(1024) void stats_kernel(const float* __restrict__ gamma,
                                                     const float* __restrict__ beta) {
    __shared__ float red[1024];
    int tid = threadIdx.x;
    int v = tid & 15, g = tid >> 4;   // 64 groups
    float s = 0.f;
    for (int i = g; i < NBLK; i += 64) s += g_part[i * 16 + v];
    red[tid] = s;
    __syncthreads();
    float tot = 0.f;
    if (tid < 16) {
        #pragma unroll
        for (int gg = 0; gg < 64; gg++) tot += red[gg * 16 + tid];
    }
    __syncthreads();
    if (tid < 16) red[tid] = tot;
    __syncthreads();
    if (tid < 8) {
        const float n = (float)(BATCH * HH * WW);
        float mean = red[tid] / n;
        float var = red[tid + 8] / n - mean * mean;
        float sc = gamma[tid] * rsqrtf(var + 1e-5f);
        g_scale[tid] = sc;
        g_shift[tid] = beta[tid] - mean * sc;
    }
}

// ---------- Kernel 3: normalize + ReLU ----------
__global__ __launch_bounds__(256) void norm_kernel(float* __restrict__ out) {
    __shared__ float ssc[8], ssh[8];
    if (threadIdx.x < 8) {
        ssc[threadIdx.x] = g_scale[threadIdx.x];
        ssh[threadIdx.x] = g_shift[threadIdx.x];
    }
    __syncthreads();
    int i = blockIdx.x * 256 + threadIdx.x;
    int c = (i >> 16) & 7;
    float4 v = ((const float4*)g_y)[i];
    float s = ssc[c], h = ssh[c];
    v.x = fmaxf(fmaf(v.x, s, h), 0.f);
    v.y = fmaxf(fmaf(v.y, s, h), 0.f);
    v.z = fmaxf(fmaf(v.z, s, h), 0.f);
    v.w = fmaxf(fmaf(v.w, s, h), 0.f);
    ((float4*)out)[i] = v;
}

extern "C" void kernel_launch(void* const* d_in, const int* in_sizes, int n_in,
                              void* d_out, int out_size) {
    const float* x     = (const float*)d_in[0];
    const float* lin_w = (const float*)d_in[1];
    const float* lin_b = (const float*)d_in[2];
    const float* gamma = (const float*)d_in[3];
    const float* beta  = (const float*)d_in[4];
    float* out = (float*)d_out;

    dim3 grid(TILES_X, TILES_Y, BATCH);
    conv_kernel<<<grid, 128>>>(x, lin_w, lin_b);
    stats_kernel<<<1, 1024>>>(gamma, beta);
    int n4 = BATCH * CHN * HH * WW / 4;
    norm_kernel<<<n4 / 256, 256>>>(out);
}